// round 2
// baseline (speedup 1.0000x reference)
#include <cuda_runtime.h>
#include <cuda_bf16.h>
#include <math.h>

// ---------------- problem constants ----------------
#define NN    8000
#define EE    24000
#define EA    32000           // E + N self loops
#define BB    256
#define ATOM  133
#define BOND  14
#define HH    256
#define HEADS 8
#define HHH   2048            // HEADS*H
#define LL    5
#define NEG   0.2f
#define EPS   1e-5f

// ---------------- scratch (static device memory; no allocation) ----------------
__device__ float g_h    [NN * HH];        // node features (updated in place per layer)
__device__ float g_xl   [NN * HHH];       // h @ Wl
__device__ float g_xr   [NN * HHH];       // h @ Wr
__device__ float g_ee   [(size_t)EA * HHH]; // ea @ We
__device__ float g_score[EA * HEADS];
__device__ float g_loop [NN * BOND];      // self-loop edge attr (mean of incoming)
__device__ int   g_cnt  [NN];             // in-degree (real edges)
__device__ int   g_off  [NN + 1];         // CSR offsets over dst (augmented)
__device__ int   g_fill [NN];
__device__ int   g_elist[EA];
__device__ float g_gate [NN];
__device__ float g_ge   [NN];
__device__ float g_gmax [BB];
__device__ float g_gsum [BB];

// ---------------- helpers ----------------
__device__ __forceinline__ float warpRedSum(float v) {
#pragma unroll
    for (int o = 16; o > 0; o >>= 1) v += __shfl_xor_sync(0xffffffffu, v, o);
    return v;
}
__device__ __forceinline__ float warpRedMax(float v) {
#pragma unroll
    for (int o = 16; o > 0; o >>= 1) v = fmaxf(v, __shfl_xor_sync(0xffffffffu, v, o));
    return v;
}

// block of 256 threads: reduce (a, b) -> broadcast sums
__device__ __forceinline__ float2 blockReduce2_256(float a, float b) {
    __shared__ float sa[8], sb[8];
    __shared__ float ra, rb;
    int lane = threadIdx.x & 31, w = threadIdx.x >> 5;
    a = warpRedSum(a); b = warpRedSum(b);
    if (lane == 0) { sa[w] = a; sb[w] = b; }
    __syncthreads();
    if (threadIdx.x == 0) {
        float ta = 0.f, tb = 0.f;
#pragma unroll
        for (int i = 0; i < 8; i++) { ta += sa[i]; tb += sb[i]; }
        ra = ta; rb = tb;
    }
    __syncthreads();
    return make_float2(ra, rb);
}

__device__ __forceinline__ void atomicMaxF(float* addr, float val) {
    int* ai = (int*)addr;
    int old = *ai;
    while (__int_as_float(old) < val) {
        int assumed = old;
        old = atomicCAS(ai, assumed, __float_as_int(val));
        if (old == assumed) break;
    }
}

// ---------------- init ----------------
__global__ void k_init(float* out) {
    int idx = blockIdx.x * blockDim.x + threadIdx.x;
    if (idx < NN) { g_cnt[idx] = 0; g_fill[idx] = 0; }
    if (idx < NN * BOND) g_loop[idx] = 0.f;
    if (idx < BB) { g_gmax[idx] = -3.4e38f; g_gsum[idx] = 0.f; }
    if (idx < BB * HH) out[idx] = 0.f;
}

// in-degree count + loop_attr numerator
__global__ void k_count(const int* __restrict__ ei, const float* __restrict__ edge_attr) {
    int e = blockIdx.x * blockDim.x + threadIdx.x;
    if (e >= EE) return;
    int d = ei[EE + e];
    atomicAdd(&g_cnt[d], 1);
#pragma unroll
    for (int k = 0; k < BOND; k++)
        atomicAdd(&g_loop[d * BOND + k], edge_attr[e * BOND + k]);
}

__global__ void k_loopfin() {
    int idx = blockIdx.x * blockDim.x + threadIdx.x;
    if (idx >= NN * BOND) return;
    int i = idx / BOND;
    g_loop[idx] /= fmaxf((float)g_cnt[i], 1.0f);
}

// exclusive scan of (cnt[i] + 1) over 8000 nodes, one block of 1024 threads
__global__ void k_scan() {
    __shared__ int s[1024];
    int t = threadIdx.x;
    int loc[8]; int sum = 0;
    int base = t * 8;
#pragma unroll
    for (int i = 0; i < 8; i++) {
        int idx = base + i;
        int v = (idx < NN) ? (g_cnt[idx] + 1) : 0;
        loc[i] = sum; sum += v;
    }
    s[t] = sum;
    __syncthreads();
    for (int off = 1; off < 1024; off <<= 1) {
        int v = 0;
        if (t >= off) v = s[t - off];
        __syncthreads();
        s[t] += v;
        __syncthreads();
    }
    int prev = (t > 0) ? s[t - 1] : 0;
#pragma unroll
    for (int i = 0; i < 8; i++) {
        int idx = base + i;
        if (idx <= NN) g_off[idx] = prev + loc[i];
    }
}

__global__ void k_fill(const int* __restrict__ ei) {
    int e = blockIdx.x * blockDim.x + threadIdx.x;
    if (e >= EA) return;
    int d = (e < EE) ? ei[EE + e] : (e - EE);
    int pos = g_off[d] + atomicAdd(&g_fill[d], 1);
    g_elist[pos] = e;
}

// ---------------- atom embedding: relu(LN(x @ W + b)) ----------------
__global__ __launch_bounds__(256) void k_embed(
    const float* __restrict__ x, const float* __restrict__ W, const float* __restrict__ b,
    const float* __restrict__ g, const float* __restrict__ beta)
{
    int i = blockIdx.x, t = threadIdx.x;
    __shared__ float xs[ATOM + 3];
    if (t < ATOM) xs[t] = x[i * ATOM + t];
    __syncthreads();
    float acc = b[t];
#pragma unroll 7
    for (int k = 0; k < ATOM; k++) acc += xs[k] * W[k * HH + t];
    float2 ss = blockReduce2_256(acc, acc * acc);
    float mean = ss.x * (1.0f / HH);
    float var  = ss.y * (1.0f / HH) - mean * mean;
    float v = (acc - mean) * rsqrtf(var + EPS) * g[t] + beta[t];
    g_h[i * HH + t] = fmaxf(v, 0.f);
}

// ---------------- big GEMM: xl = h @ Wl, xr = h @ Wr (z selects) ----------------
// M=8000, K=256, N=2048; 128x128 tile, BK=16, 256 threads, 8x8 microtile
__global__ __launch_bounds__(256, 2) void sgemm2(
    const float* __restrict__ W0, const float* __restrict__ W1)
{
    const int M = NN, Kd = HH, Nd = HHH;
    const float* W = blockIdx.z ? W1 : W0;
    float* C = blockIdx.z ? g_xr : g_xl;
    const float* A = g_h;
    __shared__ float As[16][132];
    __shared__ float Bs[16][128];
    int tid = threadIdx.x;
    int m0 = blockIdx.y * 128, n0 = blockIdx.x * 128;
    int ty = tid / 16, tx = tid % 16;
    float acc[8][8];
#pragma unroll
    for (int i = 0; i < 8; i++)
#pragma unroll
        for (int j = 0; j < 8; j++) acc[i][j] = 0.f;

    for (int k0 = 0; k0 < Kd; k0 += 16) {
#pragma unroll
        for (int it = 0; it < 2; it++) {
            int li = tid + it * 256;
            int ml = li >> 2, k4 = (li & 3) * 4;
            float4 v = make_float4(0.f, 0.f, 0.f, 0.f);
            if (m0 + ml < M)
                v = *reinterpret_cast<const float4*>(&A[(m0 + ml) * Kd + k0 + k4]);
            As[k4][ml] = v.x; As[k4 + 1][ml] = v.y; As[k4 + 2][ml] = v.z; As[k4 + 3][ml] = v.w;
        }
#pragma unroll
        for (int it = 0; it < 2; it++) {
            int li = tid + it * 256;
            int kl = li >> 5, n4 = (li & 31) * 4;
            *reinterpret_cast<float4*>(&Bs[kl][n4]) =
                *reinterpret_cast<const float4*>(&W[(k0 + kl) * Nd + n0 + n4]);
        }
        __syncthreads();
#pragma unroll
        for (int k = 0; k < 16; k++) {
            float a[8], bb[8];
            *(float4*)(a)     = *(float4*)&As[k][ty * 8];
            *(float4*)(a + 4) = *(float4*)&As[k][ty * 8 + 4];
            *(float4*)(bb)     = *(float4*)&Bs[k][tx * 8];
            *(float4*)(bb + 4) = *(float4*)&Bs[k][tx * 8 + 4];
#pragma unroll
            for (int i = 0; i < 8; i++)
#pragma unroll
                for (int j = 0; j < 8; j++) acc[i][j] += a[i] * bb[j];
        }
        __syncthreads();
    }
#pragma unroll
    for (int i = 0; i < 8; i++) {
        int m = m0 + ty * 8 + i;
        if (m < M) {
            float4* cp = (float4*)&C[(size_t)m * Nd + n0 + tx * 8];
            cp[0] = make_float4(acc[i][0], acc[i][1], acc[i][2], acc[i][3]);
            cp[1] = make_float4(acc[i][4], acc[i][5], acc[i][6], acc[i][7]);
        }
    }
}

// ---------------- ee = ea @ We (K=14 rank-k) : 64 edges x 128 cols per block ----------------
__global__ __launch_bounds__(256) void k_ee(
    const float* __restrict__ edge_attr, const float* __restrict__ We)
{
    __shared__ float eas[64 * BOND];
    __shared__ float Wes[BOND * 128];
    int tid = threadIdx.x;
    int e0 = blockIdx.y * 64, n0 = blockIdx.x * 128;
    for (int idx = tid; idx < 64 * BOND; idx += 256) {
        int r = idx / BOND, k = idx % BOND;
        int e = e0 + r;
        eas[idx] = (e < EE) ? edge_attr[e * BOND + k] : g_loop[(e - EE) * BOND + k];
    }
    for (int idx = tid; idx < BOND * 128; idx += 256) {
        int k = idx >> 7, c = idx & 127;
        Wes[idx] = We[k * HHH + n0 + c];
    }
    __syncthreads();
    int ty = tid >> 5, tx = tid & 31;
    float acc[8][4];
#pragma unroll
    for (int i = 0; i < 8; i++) { acc[i][0] = acc[i][1] = acc[i][2] = acc[i][3] = 0.f; }
#pragma unroll
    for (int k = 0; k < BOND; k++) {
        float4 wv = *(float4*)&Wes[k * 128 + tx * 4];
#pragma unroll
        for (int i = 0; i < 8; i++) {
            float a = eas[(ty * 8 + i) * BOND + k];
            acc[i][0] += a * wv.x; acc[i][1] += a * wv.y;
            acc[i][2] += a * wv.z; acc[i][3] += a * wv.w;
        }
    }
#pragma unroll
    for (int i = 0; i < 8; i++) {
        int e = e0 + ty * 8 + i;
        *(float4*)&g_ee[(size_t)e * HHH + n0 + tx * 4] =
            make_float4(acc[i][0], acc[i][1], acc[i][2], acc[i][3]);
    }
}

// ---------------- score[e,h] = sum_d lrelu(xl[s]+xr[d]+ee[e]) * att[h,d] ----------------
// 4 edges per block; warp w handles head (w&7) of edge (w>>3)... actually 8 warps:
// warps 0..7 -> edge pair layout: each block does 4 edges x 8 heads with 1 warp
// covering 2 (edge, head) slots sequentially.
__global__ __launch_bounds__(256) void k_score(
    const int* __restrict__ ei, const float* __restrict__ att)
{
    int t = threadIdx.x, lane = t & 31, w = t >> 5;   // 8 warps
    int e0 = blockIdx.x * 4;
#pragma unroll
    for (int q = 0; q < 4; q++) {
        int e = e0 + q;
        // warp w handles head w of edge e
        int s = (e < EE) ? ei[e]      : (e - EE);
        int d = (e < EE) ? ei[EE + e] : (e - EE);
        const float* xl = &g_xl[(size_t)s * HHH + w * HH];
        const float* xr = &g_xr[(size_t)d * HHH + w * HH];
        const float* ep = &g_ee[(size_t)e * HHH + w * HH];
        const float* ap = &att[w * HH];
        float acc = 0.f;
#pragma unroll
        for (int i = 0; i < 8; i++) {
            int j = lane + 32 * i;
            float v = xl[j] + xr[j] + ep[j];
            v = (v > 0.f) ? v : NEG * v;
            acc += v * ap[j];
        }
        acc = warpRedSum(acc);
        if (lane == 0) g_score[e * HEADS + w] = acc;
    }
}

// ---------------- fused per-node: softmax + aggregate + head-mean + bias + residual + LN ----------------
#define CHUNK 128
__global__ __launch_bounds__(256) void k_node(
    const int* __restrict__ ei, const float* __restrict__ bias,
    const float* __restrict__ lng, const float* __restrict__ lnb)
{
    int i = blockIdx.x, t = threadIdx.x, lane = t & 31, w = t >> 5;
    __shared__ float s_max[8], s_rcp[8];
    __shared__ float s_alpha[CHUNK * 8];
    __shared__ int   s_src[CHUNK];
    int beg = g_off[i], end = g_off[i + 1], m = end - beg;

    // phase A: per-head max (warp w handles head w)
    float mv = -3.4e38f;
    for (int p = lane; p < m; p += 32) {
        int e = g_elist[beg + p];
        mv = fmaxf(mv, g_score[e * HEADS + w]);
    }
    mv = warpRedMax(mv);
    if (lane == 0) s_max[w] = mv;
    __syncthreads();

    // phase B: per-head sum of exp
    float mh = s_max[w];
    float sum = 0.f;
    for (int p = lane; p < m; p += 32) {
        int e = g_elist[beg + p];
        sum += expf(g_score[e * HEADS + w] - mh);
    }
    sum = warpRedSum(sum);
    if (lane == 0) s_rcp[w] = 1.0f / sum;
    __syncthreads();

    // phase C: weighted aggregation of xl[src] (chunked)
    float acc[8];
#pragma unroll
    for (int h = 0; h < 8; h++) acc[h] = 0.f;
    for (int c0 = 0; c0 < m; c0 += CHUNK) {
        int cm = min(CHUNK, m - c0);
        for (int p = t; p < cm * 8; p += 256) {
            int idx = p >> 3, h = p & 7;
            int e = g_elist[beg + c0 + idx];
            s_alpha[p] = expf(g_score[e * HEADS + h] - s_max[h]) * s_rcp[h];
            if (h == 0) s_src[idx] = (e < EE) ? ei[e] : (e - EE);
        }
        __syncthreads();
        for (int idx = 0; idx < cm; idx++) {
            const float* xp = &g_xl[(size_t)s_src[idx] * HHH + t];
            const float* ap = &s_alpha[idx * 8];
#pragma unroll
            for (int h = 0; h < 8; h++) acc[h] += ap[h] * xp[h * HH];
        }
        __syncthreads();
    }

    // phase D: head mean + bias + residual + LN
    float o = (acc[0] + acc[1] + acc[2] + acc[3] + acc[4] + acc[5] + acc[6] + acc[7]) * 0.125f
              + bias[t] + g_h[i * HH + t];
    float2 ss = blockReduce2_256(o, o * o);
    float mean = ss.x * (1.0f / HH);
    float var  = ss.y * (1.0f / HH) - mean * mean;
    g_h[i * HH + t] = (o - mean) * rsqrtf(var + EPS) * lng[t] + lnb[t];
}

// ---------------- readout ----------------
__global__ __launch_bounds__(128) void k_gate(
    const float* __restrict__ g1W, const float* __restrict__ g1b,
    const float* __restrict__ g2W, const float* __restrict__ g2b)
{
    int i = blockIdx.x, t = threadIdx.x;   // 128 threads
    __shared__ float hs[HH];
    __shared__ float red[4];
    hs[t] = g_h[i * HH + t];
    hs[t + 128] = g_h[i * HH + t + 128];
    __syncthreads();
    float acc = g1b[t];
#pragma unroll 8
    for (int k = 0; k < HH; k++) acc += hs[k] * g1W[k * 128 + t];
    float v = fmaxf(acc, 0.f) * g2W[t];
    v = warpRedSum(v);
    if ((t & 31) == 0) red[t >> 5] = v;
    __syncthreads();
    if (t == 0) g_gate[i] = red[0] + red[1] + red[2] + red[3] + g2b[0];
}

__global__ void k_gmax(const int* __restrict__ batch) {
    int i = blockIdx.x * blockDim.x + threadIdx.x;
    if (i >= NN) return;
    atomicMaxF(&g_gmax[batch[i]], g_gate[i]);
}
__global__ void k_gsum(const int* __restrict__ batch) {
    int i = blockIdx.x * blockDim.x + threadIdx.x;
    if (i >= NN) return;
    float ge = expf(g_gate[i] - g_gmax[batch[i]]);
    g_ge[i] = ge;
    atomicAdd(&g_gsum[batch[i]], ge);
}
__global__ __launch_bounds__(256) void k_out(const int* __restrict__ batch, float* __restrict__ out) {
    int i = blockIdx.x, t = threadIdx.x;
    int b = batch[i];
    float w = g_ge[i] / fmaxf(g_gsum[b], 1e-16f);
    atomicAdd(&out[b * HH + t], w * g_h[i * HH + t]);
}

// ---------------- launch ----------------
extern "C" void kernel_launch(void* const* d_in, const int* in_sizes, int n_in,
                              void* d_out, int out_size)
{
    const float* x        = (const float*)d_in[0];
    const float* edge_attr= (const float*)d_in[1];
    const float* emb_W    = (const float*)d_in[2];
    const float* emb_b    = (const float*)d_in[3];
    const float* emb_g    = (const float*)d_in[4];
    const float* emb_beta = (const float*)d_in[5];
    const float* Wl       = (const float*)d_in[6];
    const float* Wr       = (const float*)d_in[7];
    const float* We       = (const float*)d_in[8];
    const float* att      = (const float*)d_in[9];
    const float* bias     = (const float*)d_in[10];
    const float* ln_g     = (const float*)d_in[11];
    const float* ln_b     = (const float*)d_in[12];
    const float* g1W      = (const float*)d_in[13];
    const float* g1b      = (const float*)d_in[14];
    const float* g2W      = (const float*)d_in[15];
    const float* g2b      = (const float*)d_in[16];
    const int*   ei       = (const int*)d_in[17];
    const int*   batch    = (const int*)d_in[18];
    float* out = (float*)d_out;

    k_init<<<(NN * BOND + 255) / 256, 256>>>(out);
    k_count<<<(EE + 255) / 256, 256>>>(ei, edge_attr);
    k_loopfin<<<(NN * BOND + 255) / 256, 256>>>();
    k_scan<<<1, 1024>>>();
    k_fill<<<(EA + 255) / 256, 256>>>(ei);
    k_embed<<<NN, 256>>>(x, emb_W, emb_b, emb_g, emb_beta);

    for (int l = 0; l < LL; l++) {
        sgemm2<<<dim3(HHH / 128, (NN + 127) / 128, 2), 256>>>(
            Wl + (size_t)l * HH * HHH, Wr + (size_t)l * HH * HHH);
        k_ee<<<dim3(HHH / 128, EA / 64), 256>>>(edge_attr, We + (size_t)l * BOND * HHH);
        k_score<<<EA / 4, 256>>>(ei, att + (size_t)l * HEADS * HH);
        k_node<<<NN, 256>>>(ei, bias + l * HH, ln_g + l * HH, ln_b + l * HH);
    }

    k_gate<<<NN, 128>>>(g1W, g1b, g2W, g2b);
    k_gmax<<<(NN + 255) / 256, 256>>>(batch);
    k_gsum<<<(NN + 255) / 256, 256>>>(batch);
    k_out<<<NN, 256>>>(batch, out);
}

// round 10
// speedup vs baseline: 1.0756x; 1.0756x over previous
#include <cuda_runtime.h>
#include <cuda_bf16.h>
#include <mma.h>
#include <math.h>
#include <stdint.h>

using namespace nvcuda;

// ---------------- problem constants ----------------
#define NN    8000
#define EE    24000
#define EA    32000           // E + N self loops
#define BB    256
#define ATOM  133
#define BOND  14
#define HH    256
#define HEADS 8
#define HHH   2048            // HEADS*H
#define LL    5
#define NEG   0.2f
#define EPS   1e-5f

// ---------------- scratch (static device memory; no allocation) ----------------
__device__ float g_h    [NN * HH];
__device__ float g_xl   [NN * HHH];
__device__ float g_xr   [NN * HHH];
__device__ float g_score[EA * HEADS];
__device__ float g_loop [NN * BOND];
__device__ int   g_cnt  [NN];
__device__ int   g_off  [NN + 1];
__device__ int   g_fill [NN];
__device__ int   g_elist[EA];
__device__ float g_gate [NN];
__device__ float g_ge   [NN];
__device__ float g_gmax [BB];
__device__ float g_gsum [BB];
// bf16 split operands for tensor-core GEMM
__device__ __nv_bfloat16 g_ahi[NN * HH];
__device__ __nv_bfloat16 g_alo[NN * HH];
__device__ __nv_bfloat16 g_whi[2 * HH * HHH];   // [z][k][n] row-major
__device__ __nv_bfloat16 g_wlo[2 * HH * HHH];

// ---------------- generic helpers ----------------
__device__ __forceinline__ float warpRedSum(float v) {
#pragma unroll
    for (int o = 16; o > 0; o >>= 1) v += __shfl_xor_sync(0xffffffffu, v, o);
    return v;
}
__device__ __forceinline__ float warpRedMax(float v) {
#pragma unroll
    for (int o = 16; o > 0; o >>= 1) v = fmaxf(v, __shfl_xor_sync(0xffffffffu, v, o));
    return v;
}
__device__ __forceinline__ float2 blockReduce2_256(float a, float b) {
    __shared__ float sa[8], sb[8];
    __shared__ float ra, rb;
    int lane = threadIdx.x & 31, w = threadIdx.x >> 5;
    a = warpRedSum(a); b = warpRedSum(b);
    if (lane == 0) { sa[w] = a; sb[w] = b; }
    __syncthreads();
    if (threadIdx.x == 0) {
        float ta = 0.f, tb = 0.f;
#pragma unroll
        for (int i = 0; i < 8; i++) { ta += sa[i]; tb += sb[i]; }
        ra = ta; rb = tb;
    }
    __syncthreads();
    return make_float2(ra, rb);
}
__device__ __forceinline__ void atomicMaxF(float* addr, float val) {
    int* ai = (int*)addr;
    int old = *ai;
    while (__int_as_float(old) < val) {
        int assumed = old;
        old = atomicCAS(ai, assumed, __float_as_int(val));
        if (old == assumed) break;
    }
}
// store h value + bf16 hi/lo split in one place
__device__ __forceinline__ void store_h_split(int idx, float v) {
    g_h[idx] = v;
    __nv_bfloat16 hi = __float2bfloat16(v);
    g_ahi[idx] = hi;
    g_alo[idx] = __float2bfloat16(v - __bfloat162float(hi));
}

// ---------------- init / CSR build ----------------
__global__ void k_init(float* out) {
    int idx = blockIdx.x * blockDim.x + threadIdx.x;
    if (idx < NN) { g_cnt[idx] = 0; g_fill[idx] = 0; }
    if (idx < NN * BOND) g_loop[idx] = 0.f;
    if (idx < BB) { g_gmax[idx] = -3.4e38f; g_gsum[idx] = 0.f; }
    if (idx < BB * HH) out[idx] = 0.f;
}
__global__ void k_count(const int* __restrict__ ei, const float* __restrict__ edge_attr) {
    int e = blockIdx.x * blockDim.x + threadIdx.x;
    if (e >= EE) return;
    int d = ei[EE + e];
    atomicAdd(&g_cnt[d], 1);
#pragma unroll
    for (int k = 0; k < BOND; k++)
        atomicAdd(&g_loop[d * BOND + k], edge_attr[e * BOND + k]);
}
__global__ void k_loopfin() {
    int idx = blockIdx.x * blockDim.x + threadIdx.x;
    if (idx >= NN * BOND) return;
    int i = idx / BOND;
    g_loop[idx] /= fmaxf((float)g_cnt[i], 1.0f);
}
__global__ void k_scan() {
    __shared__ int s[1024];
    int t = threadIdx.x;
    int loc[8]; int sum = 0;
    int base = t * 8;
#pragma unroll
    for (int i = 0; i < 8; i++) {
        int idx = base + i;
        int v = (idx < NN) ? (g_cnt[idx] + 1) : 0;
        loc[i] = sum; sum += v;
    }
    s[t] = sum;
    __syncthreads();
    for (int off = 1; off < 1024; off <<= 1) {
        int v = 0;
        if (t >= off) v = s[t - off];
        __syncthreads();
        s[t] += v;
        __syncthreads();
    }
    int prev = (t > 0) ? s[t - 1] : 0;
#pragma unroll
    for (int i = 0; i < 8; i++) {
        int idx = base + i;
        if (idx <= NN) g_off[idx] = prev + loc[i];
    }
}
__global__ void k_fill(const int* __restrict__ ei) {
    int e = blockIdx.x * blockDim.x + threadIdx.x;
    if (e >= EA) return;
    int d = (e < EE) ? ei[EE + e] : (e - EE);
    int pos = g_off[d] + atomicAdd(&g_fill[d], 1);
    g_elist[pos] = e;
}

// ---------------- atom embedding ----------------
__global__ __launch_bounds__(256) void k_embed(
    const float* __restrict__ x, const float* __restrict__ W, const float* __restrict__ b,
    const float* __restrict__ g, const float* __restrict__ beta)
{
    int i = blockIdx.x, t = threadIdx.x;
    __shared__ float xs[ATOM + 3];
    if (t < ATOM) xs[t] = x[i * ATOM + t];
    __syncthreads();
    float acc = b[t];
#pragma unroll 7
    for (int k = 0; k < ATOM; k++) acc += xs[k] * W[k * HH + t];
    float2 ss = blockReduce2_256(acc, acc * acc);
    float mean = ss.x * (1.0f / HH);
    float var  = ss.y * (1.0f / HH) - mean * mean;
    float v = (acc - mean) * rsqrtf(var + EPS) * g[t] + beta[t];
    store_h_split(i * HH + t, fmaxf(v, 0.f));
}

// ---------------- weight bf16 split conversion ----------------
__global__ void k_cvtW(const float* __restrict__ Wl, const float* __restrict__ Wr) {
    size_t idx = (size_t)blockIdx.x * blockDim.x + threadIdx.x;
    if (idx >= (size_t)HH * HHH) return;
    const float* W = blockIdx.y ? Wr : Wl;
    size_t o = (size_t)blockIdx.y * HH * HHH + idx;
    float v = W[idx];
    __nv_bfloat16 hi = __float2bfloat16(v);
    g_whi[o] = hi;
    g_wlo[o] = __float2bfloat16(v - __bfloat162float(hi));
}

// ---------------- WMMA split-bf16 GEMM ----------------
// C[8000 x 2048] = A[8000 x 256] * W[256 x 2048]  (z: 0 -> xl, 1 -> xr)
// block tile 128x128, 8 warps (4m x 2n), warp tile 32x64, BK=32
#define BK     32
#define LDA    40
#define LDB    136
__global__ __launch_bounds__(256) void wgemm()
{
    __shared__ __align__(16) __nv_bfloat16 As_hi[128 * LDA];
    __shared__ __align__(16) __nv_bfloat16 As_lo[128 * LDA];
    __shared__ __align__(16) __nv_bfloat16 Bs_hi[BK * LDB];
    __shared__ __align__(16) __nv_bfloat16 Bs_lo[BK * LDB];

    int tid = threadIdx.x, wid = tid >> 5;
    int m0 = blockIdx.y * 128, n0 = blockIdx.x * 128;
    int wm = wid & 3, wn = wid >> 2;          // 4 x 2 warp grid
    size_t zoff = (size_t)blockIdx.z * HH * HHH;
    const __nv_bfloat16* Bhi = g_whi + zoff;
    const __nv_bfloat16* Blo = g_wlo + zoff;
    float* C = blockIdx.z ? g_xr : g_xl;

    wmma::fragment<wmma::accumulator, 16, 16, 16, float> acc[2][4];
#pragma unroll
    for (int i = 0; i < 2; i++)
#pragma unroll
        for (int j = 0; j < 4; j++) wmma::fill_fragment(acc[i][j], 0.f);

#pragma unroll 1
    for (int k0 = 0; k0 < HH; k0 += BK) {
        // load A tile: 128 rows x 32 k, hi+lo (512 uint4 each)
#pragma unroll
        for (int it = 0; it < 2; it++) {
            int li = tid + it * 256;            // 0..511
            int r = li >> 2, kv = (li & 3) * 8;
            uint4 vh = make_uint4(0u, 0u, 0u, 0u), vl = vh;
            int gm = m0 + r;
            if (gm < NN) {
                size_t gi = (size_t)gm * HH + k0 + kv;
                vh = *(const uint4*)(g_ahi + gi);
                vl = *(const uint4*)(g_alo + gi);
            }
            *(uint4*)(As_hi + r * LDA + kv) = vh;
            *(uint4*)(As_lo + r * LDA + kv) = vl;
        }
        // load B tile: 32 k x 128 n, hi+lo
#pragma unroll
        for (int it = 0; it < 2; it++) {
            int li = tid + it * 256;
            int r = li >> 4, nv = (li & 15) * 8;
            size_t gi = (size_t)(k0 + r) * HHH + n0 + nv;
            *(uint4*)(Bs_hi + r * LDB + nv) = *(const uint4*)(Bhi + gi);
            *(uint4*)(Bs_lo + r * LDB + nv) = *(const uint4*)(Blo + gi);
        }
        __syncthreads();

#pragma unroll
        for (int kk = 0; kk < BK; kk += 16) {
            wmma::fragment<wmma::matrix_a, 16, 16, 16, __nv_bfloat16, wmma::row_major> a_hi[2], a_lo[2];
#pragma unroll
            for (int i = 0; i < 2; i++) {
                wmma::load_matrix_sync(a_hi[i], As_hi + (wm * 32 + i * 16) * LDA + kk, LDA);
                wmma::load_matrix_sync(a_lo[i], As_lo + (wm * 32 + i * 16) * LDA + kk, LDA);
            }
#pragma unroll
            for (int j = 0; j < 4; j++) {
                wmma::fragment<wmma::matrix_b, 16, 16, 16, __nv_bfloat16, wmma::row_major> b_hi, b_lo;
                wmma::load_matrix_sync(b_hi, Bs_hi + kk * LDB + wn * 64 + j * 16, LDB);
                wmma::load_matrix_sync(b_lo, Bs_lo + kk * LDB + wn * 64 + j * 16, LDB);
#pragma unroll
                for (int i = 0; i < 2; i++) {
                    wmma::mma_sync(acc[i][j], a_hi[i], b_hi, acc[i][j]);
                    wmma::mma_sync(acc[i][j], a_hi[i], b_lo, acc[i][j]);
                    wmma::mma_sync(acc[i][j], a_lo[i], b_hi, acc[i][j]);
                }
            }
        }
        __syncthreads();
    }

    // epilogue: NN % 32 == 0, so each 16-row tile is fully in or out
#pragma unroll
    for (int i = 0; i < 2; i++) {
        int mrow = m0 + wm * 32 + i * 16;
        if (mrow + 16 <= NN) {
#pragma unroll
            for (int j = 0; j < 4; j++) {
                float* cp = C + (size_t)mrow * HHH + n0 + wn * 64 + j * 16;
                wmma::store_matrix_sync(cp, acc[i][j], HHH, wmma::mem_row_major);
            }
        }
    }
}

// ---------------- fused attention scores (ee computed on the fly) ----------------
// grid: (EA/64, HEADS), block 256 = 8 warps, each warp does 8 edges of head blockIdx.y
__global__ __launch_bounds__(256) void k_score_f(
    const int* __restrict__ ei, const float* __restrict__ edge_attr,
    const float* __restrict__ att, const float* __restrict__ We)
{
    int h = blockIdx.y;
    __shared__ float sW[BOND][HH];     // 14 KB: We[:, h*256 : (h+1)*256]
    __shared__ float sAtt[HH];
    int tid = threadIdx.x, lane = tid & 31, w = tid >> 5;
    for (int idx = tid; idx < BOND * HH; idx += 256) {
        int k = idx >> 8, c = idx & 255;
        sW[k][c] = We[k * HHH + h * HH + c];
    }
    sAtt[tid] = att[h * HH + tid];
    __syncthreads();

    int e0 = blockIdx.x * 64;
#pragma unroll 1
    for (int q = w; q < 64; q += 8) {
        int e = e0 + q;
        int s = (e < EE) ? ei[e]      : (e - EE);
        int d = (e < EE) ? ei[EE + e] : (e - EE);
        const float* eap = (e < EE) ? &edge_attr[(size_t)e * BOND] : &g_loop[(size_t)(e - EE) * BOND];
        float ea[BOND];
#pragma unroll
        for (int k = 0; k < BOND; k++) ea[k] = eap[k];
        const float* xl = &g_xl[(size_t)s * HHH + h * HH];
        const float* xr = &g_xr[(size_t)d * HHH + h * HH];
        float acc = 0.f;
#pragma unroll
        for (int i = 0; i < 8; i++) {
            int j = lane + 32 * i;
            float eev = 0.f;
#pragma unroll
            for (int k = 0; k < BOND; k++) eev += ea[k] * sW[k][j];
            float v = xl[j] + xr[j] + eev;
            v = (v > 0.f) ? v : NEG * v;
            acc += v * sAtt[j];
        }
        acc = warpRedSum(acc);
        if (lane == 0) g_score[e * HEADS + h] = acc;
    }
}

// ---------------- fused per-node softmax/aggregate/LN ----------------
#define CHUNK 128
__global__ __launch_bounds__(256) void k_node(
    const int* __restrict__ ei, const float* __restrict__ bias,
    const float* __restrict__ lng, const float* __restrict__ lnb)
{
    int i = blockIdx.x, t = threadIdx.x, lane = t & 31, w = t >> 5;
    __shared__ float s_max[8], s_rcp[8];
    __shared__ float s_alpha[CHUNK * 8];
    __shared__ int   s_src[CHUNK];
    int beg = g_off[i], end = g_off[i + 1], m = end - beg;

    float mv = -3.4e38f;
    for (int p = lane; p < m; p += 32) {
        int e = g_elist[beg + p];
        mv = fmaxf(mv, g_score[e * HEADS + w]);
    }
    mv = warpRedMax(mv);
    if (lane == 0) s_max[w] = mv;
    __syncthreads();

    float mh = s_max[w];
    float sum = 0.f;
    for (int p = lane; p < m; p += 32) {
        int e = g_elist[beg + p];
        sum += expf(g_score[e * HEADS + w] - mh);
    }
    sum = warpRedSum(sum);
    if (lane == 0) s_rcp[w] = 1.0f / sum;
    __syncthreads();

    float acc[8];
#pragma unroll
    for (int h = 0; h < 8; h++) acc[h] = 0.f;
    for (int c0 = 0; c0 < m; c0 += CHUNK) {
        int cm = min(CHUNK, m - c0);
        for (int p = t; p < cm * 8; p += 256) {
            int idx = p >> 3, h = p & 7;
            int e = g_elist[beg + c0 + idx];
            s_alpha[p] = expf(g_score[e * HEADS + h] - s_max[h]) * s_rcp[h];
            if (h == 0) s_src[idx] = (e < EE) ? ei[e] : (e - EE);
        }
        __syncthreads();
        for (int idx = 0; idx < cm; idx++) {
            const float* xp = &g_xl[(size_t)s_src[idx] * HHH + t];
            const float* ap = &s_alpha[idx * 8];
#pragma unroll
            for (int h = 0; h < 8; h++) acc[h] += ap[h] * xp[h * HH];
        }
        __syncthreads();
    }

    float o = (acc[0] + acc[1] + acc[2] + acc[3] + acc[4] + acc[5] + acc[6] + acc[7]) * 0.125f
              + bias[t] + g_h[i * HH + t];
    float2 ss = blockReduce2_256(o, o * o);
    float mean = ss.x * (1.0f / HH);
    float var  = ss.y * (1.0f / HH) - mean * mean;
    store_h_split(i * HH + t, (o - mean) * rsqrtf(var + EPS) * lng[t] + lnb[t]);
}

// ---------------- readout ----------------
__global__ __launch_bounds__(128) void k_gate(
    const float* __restrict__ g1W, const float* __restrict__ g1b,
    const float* __restrict__ g2W, const float* __restrict__ g2b)
{
    int i = blockIdx.x, t = threadIdx.x;
    __shared__ float hs[HH];
    __shared__ float red[4];
    hs[t] = g_h[i * HH + t];
    hs[t + 128] = g_h[i * HH + t + 128];
    __syncthreads();
    float acc = g1b[t];
#pragma unroll 8
    for (int k = 0; k < HH; k++) acc += hs[k] * g1W[k * 128 + t];
    float v = fmaxf(acc, 0.f) * g2W[t];
    v = warpRedSum(v);
    if ((t & 31) == 0) red[t >> 5] = v;
    __syncthreads();
    if (t == 0) g_gate[i] = red[0] + red[1] + red[2] + red[3] + g2b[0];
}
__global__ void k_gmax(const int* __restrict__ batch) {
    int i = blockIdx.x * blockDim.x + threadIdx.x;
    if (i >= NN) return;
    atomicMaxF(&g_gmax[batch[i]], g_gate[i]);
}
__global__ void k_gsum(const int* __restrict__ batch) {
    int i = blockIdx.x * blockDim.x + threadIdx.x;
    if (i >= NN) return;
    float ge = expf(g_gate[i] - g_gmax[batch[i]]);
    g_ge[i] = ge;
    atomicAdd(&g_gsum[batch[i]], ge);
}
__global__ __launch_bounds__(256) void k_out(const int* __restrict__ batch, float* __restrict__ out) {
    int i = blockIdx.x, t = threadIdx.x;
    int b = batch[i];
    float w = g_ge[i] / fmaxf(g_gsum[b], 1e-16f);
    atomicAdd(&out[b * HH + t], w * g_h[i * HH + t]);
}

// ---------------- launch ----------------
extern "C" void kernel_launch(void* const* d_in, const int* in_sizes, int n_in,
                              void* d_out, int out_size)
{
    const float* x        = (const float*)d_in[0];
    const float* edge_attr= (const float*)d_in[1];
    const float* emb_W    = (const float*)d_in[2];
    const float* emb_b    = (const float*)d_in[3];
    const float* emb_g    = (const float*)d_in[4];
    const float* emb_beta = (const float*)d_in[5];
    const float* Wl       = (const float*)d_in[6];
    const float* Wr       = (const float*)d_in[7];
    const float* We       = (const float*)d_in[8];
    const float* att      = (const float*)d_in[9];
    const float* bias     = (const float*)d_in[10];
    const float* ln_g     = (const float*)d_in[11];
    const float* ln_b     = (const float*)d_in[12];
    const float* g1W      = (const float*)d_in[13];
    const float* g1b      = (const float*)d_in[14];
    const float* g2W      = (const float*)d_in[15];
    const float* g2b      = (const float*)d_in[16];
    const int*   ei       = (const int*)d_in[17];
    const int*   batch    = (const int*)d_in[18];
    float* out = (float*)d_out;

    k_init<<<(NN * BOND + 255) / 256, 256>>>(out);
    k_count<<<(EE + 255) / 256, 256>>>(ei, edge_attr);
    k_loopfin<<<(NN * BOND + 255) / 256, 256>>>();
    k_scan<<<1, 1024>>>();
    k_fill<<<(EA + 255) / 256, 256>>>(ei);
    k_embed<<<NN, 256>>>(x, emb_W, emb_b, emb_g, emb_beta);

    for (int l = 0; l < LL; l++) {
        k_cvtW<<<dim3((HH * HHH + 255) / 256, 2), 256>>>(
            Wl + (size_t)l * HH * HHH, Wr + (size_t)l * HH * HHH);
        wgemm<<<dim3(HHH / 128, (NN + 127) / 128, 2), 256>>>();
        k_score_f<<<dim3(EA / 64, HEADS), 256>>>(
            ei, edge_attr, att + (size_t)l * HEADS * HH, We + (size_t)l * BOND * HHH);
        k_node<<<NN, 256>>>(ei, bias + l * HH, ln_g + l * HH, ln_b + l * HH);
    }

    k_gate<<<NN, 128>>>(g1W, g1b, g2W, g2b);
    k_gmax<<<(NN + 255) / 256, 256>>>(batch);
    k_gsum<<<(NN + 255) / 256, 256>>>(batch);
    k_out<<<NN, 256>>>(batch, out);
}

// round 13
// speedup vs baseline: 1.0927x; 1.0158x over previous
#include <cuda_runtime.h>
#include <cuda_bf16.h>
#include <mma.h>
#include <math.h>
#include <stdint.h>

using namespace nvcuda;

// ---------------- problem constants ----------------
#define NN    8000
#define EE    24000
#define EA    32000           // E + N self loops
#define BB    256
#define ATOM  133
#define BOND  14
#define HH    256
#define HEADS 8
#define HHH   2048            // HEADS*H
#define LL    5
#define NEG   0.2f
#define EPS   1e-5f

// ---------------- scratch (static device memory; no allocation) ----------------
__device__ float g_h    [NN * HH];
__device__ float g_xl   [NN * HHH];
__device__ float g_xr   [NN * HHH];
__device__ float g_score[EA * HEADS];     // position-indexed (CSR order)
__device__ float g_loop [NN * BOND];
__device__ int   g_cnt  [NN];
__device__ int   g_off  [NN + 1];
__device__ int   g_fill [NN];
__device__ int   g_elist[EA];             // pos -> original edge id
__device__ int   g_esrc [EA];             // pos -> src node
__device__ int   g_edst [EA];             // pos -> dst node
__device__ float g_gate [NN];
__device__ float g_ge   [NN];
__device__ float g_gmax [BB];
__device__ float g_gsum [BB];
// bf16 split operands for tensor-core GEMM
__device__ __nv_bfloat16 g_ahi[NN * HH];
__device__ __nv_bfloat16 g_alo[NN * HH];
__device__ __nv_bfloat16 g_whi[2 * HH * HHH];   // [z][k][n] row-major
__device__ __nv_bfloat16 g_wlo[2 * HH * HHH];

// ---------------- generic helpers ----------------
__device__ __forceinline__ float warpRedSum(float v) {
#pragma unroll
    for (int o = 16; o > 0; o >>= 1) v += __shfl_xor_sync(0xffffffffu, v, o);
    return v;
}
__device__ __forceinline__ float warpRedMax(float v) {
#pragma unroll
    for (int o = 16; o > 0; o >>= 1) v = fmaxf(v, __shfl_xor_sync(0xffffffffu, v, o));
    return v;
}
__device__ __forceinline__ float2 blockReduce2_256(float a, float b) {
    __shared__ float sa[8], sb[8];
    __shared__ float ra, rb;
    int lane = threadIdx.x & 31, w = threadIdx.x >> 5;
    a = warpRedSum(a); b = warpRedSum(b);
    if (lane == 0) { sa[w] = a; sb[w] = b; }
    __syncthreads();
    if (threadIdx.x == 0) {
        float ta = 0.f, tb = 0.f;
#pragma unroll
        for (int i = 0; i < 8; i++) { ta += sa[i]; tb += sb[i]; }
        ra = ta; rb = tb;
    }
    __syncthreads();
    return make_float2(ra, rb);
}
__device__ __forceinline__ void atomicMaxF(float* addr, float val) {
    int* ai = (int*)addr;
    int old = *ai;
    while (__int_as_float(old) < val) {
        int assumed = old;
        old = atomicCAS(ai, assumed, __float_as_int(val));
        if (old == assumed) break;
    }
}
__device__ __forceinline__ void store_h_split(int idx, float v) {
    g_h[idx] = v;
    __nv_bfloat16 hi = __float2bfloat16(v);
    g_ahi[idx] = hi;
    g_alo[idx] = __float2bfloat16(v - __bfloat162float(hi));
}
// 16B cp.async with zero-fill when src_bytes == 0
__device__ __forceinline__ void cp16(uint32_t dst_smem, const void* src, int src_bytes) {
    asm volatile("cp.async.cg.shared.global [%0], [%1], 16, %2;\n"
                 :: "r"(dst_smem), "l"(src), "r"(src_bytes));
}

// ---------------- init / CSR build ----------------
__global__ void k_init(float* out) {
    int idx = blockIdx.x * blockDim.x + threadIdx.x;
    if (idx < NN) { g_cnt[idx] = 0; g_fill[idx] = 0; }
    if (idx < NN * BOND) g_loop[idx] = 0.f;
    if (idx < BB) { g_gmax[idx] = -3.4e38f; g_gsum[idx] = 0.f; }
    if (idx < BB * HH) out[idx] = 0.f;
}
__global__ void k_count(const int* __restrict__ ei, const float* __restrict__ edge_attr) {
    int e = blockIdx.x * blockDim.x + threadIdx.x;
    if (e >= EE) return;
    int d = ei[EE + e];
    atomicAdd(&g_cnt[d], 1);
#pragma unroll
    for (int k = 0; k < BOND; k++)
        atomicAdd(&g_loop[d * BOND + k], edge_attr[e * BOND + k]);
}
__global__ void k_loopfin() {
    int idx = blockIdx.x * blockDim.x + threadIdx.x;
    if (idx >= NN * BOND) return;
    int i = idx / BOND;
    g_loop[idx] /= fmaxf((float)g_cnt[i], 1.0f);
}
__global__ void k_scan() {
    __shared__ int s[1024];
    int t = threadIdx.x;
    int loc[8]; int sum = 0;
    int base = t * 8;
#pragma unroll
    for (int i = 0; i < 8; i++) {
        int idx = base + i;
        int v = (idx < NN) ? (g_cnt[idx] + 1) : 0;
        loc[i] = sum; sum += v;
    }
    s[t] = sum;
    __syncthreads();
    for (int off = 1; off < 1024; off <<= 1) {
        int v = 0;
        if (t >= off) v = s[t - off];
        __syncthreads();
        s[t] += v;
        __syncthreads();
    }
    int prev = (t > 0) ? s[t - 1] : 0;
#pragma unroll
    for (int i = 0; i < 8; i++) {
        int idx = base + i;
        if (idx <= NN) g_off[idx] = prev + loc[i];
    }
}
__global__ void k_fill(const int* __restrict__ ei) {
    int e = blockIdx.x * blockDim.x + threadIdx.x;
    if (e >= EA) return;
    int s = (e < EE) ? ei[e]      : (e - EE);
    int d = (e < EE) ? ei[EE + e] : (e - EE);
    int pos = g_off[d] + atomicAdd(&g_fill[d], 1);
    g_elist[pos] = e;
    g_esrc[pos] = s;
    g_edst[pos] = d;
}

// ---------------- atom embedding ----------------
__global__ __launch_bounds__(256) void k_embed(
    const float* __restrict__ x, const float* __restrict__ W, const float* __restrict__ b,
    const float* __restrict__ g, const float* __restrict__ beta)
{
    int i = blockIdx.x, t = threadIdx.x;
    __shared__ float xs[ATOM + 3];
    if (t < ATOM) xs[t] = x[i * ATOM + t];
    __syncthreads();
    float acc = b[t];
#pragma unroll 7
    for (int k = 0; k < ATOM; k++) acc += xs[k] * W[k * HH + t];
    float2 ss = blockReduce2_256(acc, acc * acc);
    float mean = ss.x * (1.0f / HH);
    float var  = ss.y * (1.0f / HH) - mean * mean;
    float v = (acc - mean) * rsqrtf(var + EPS) * g[t] + beta[t];
    store_h_split(i * HH + t, fmaxf(v, 0.f));
}

// ---------------- weight bf16 split conversion ----------------
__global__ void k_cvtW(const float* __restrict__ Wl, const float* __restrict__ Wr) {
    size_t idx = (size_t)blockIdx.x * blockDim.x + threadIdx.x;
    if (idx >= (size_t)HH * HHH) return;
    const float* W = blockIdx.y ? Wr : Wl;
    size_t o = (size_t)blockIdx.y * HH * HHH + idx;
    float v = W[idx];
    __nv_bfloat16 hi = __float2bfloat16(v);
    g_whi[o] = hi;
    g_wlo[o] = __float2bfloat16(v - __bfloat162float(hi));
}

// ---------------- WMMA split-bf16 GEMM, 2-stage cp.async pipeline ----------------
// C[8000 x 2048] = A[8000 x 256] * W[256 x 2048]  (z: 0 -> xl, 1 -> xr)
// block tile 128x128, 8 warps (4m x 2n), warp tile 32x64, BK=32
#define BK     32
#define LDA    40
#define LDB    136
#define OFF_ALO (128 * LDA)
#define OFF_BHI (2 * 128 * LDA)
#define OFF_BLO (2 * 128 * LDA + BK * LDB)
#define STAGE_ELEMS (2 * 128 * LDA + 2 * BK * LDB)   // 18944 bf16 = 37888 B
#define WG_SMEM (2 * STAGE_ELEMS * 2)                // 75776 B

__global__ __launch_bounds__(256) void wgemm()
{
    extern __shared__ __align__(16) __nv_bfloat16 sm[];
    int tid = threadIdx.x, wid = tid >> 5;
    int m0 = blockIdx.y * 128, n0 = blockIdx.x * 128;
    int wm = wid & 3, wn = wid >> 2;
    size_t zoff = (size_t)blockIdx.z * HH * HHH;
    const __nv_bfloat16* Bhi = g_whi + zoff;
    const __nv_bfloat16* Blo = g_wlo + zoff;
    float* C = blockIdx.z ? g_xr : g_xl;

    // per-thread load coordinates (fixed across stages)
    int ar[2], akv[2], asz[2];
    size_t agi[2];
    int br[2], bnv[2];
    size_t bgi_rel[2];
#pragma unroll
    for (int it = 0; it < 2; it++) {
        int li = tid + it * 256;
        ar[it] = li >> 2; akv[it] = (li & 3) * 8;
        int gm = m0 + ar[it];
        asz[it] = (gm < NN) ? 16 : 0;
        agi[it] = (size_t)((gm < NN) ? gm : 0) * HH + akv[it];
        br[it] = li >> 4; bnv[it] = (li & 15) * 8;
        bgi_rel[it] = (size_t)br[it] * HHH + n0 + bnv[it];
    }

    uint32_t smb = (uint32_t)__cvta_generic_to_shared(sm);

    auto load_stage = [&](int s, int k0) {
        uint32_t sa = smb + (uint32_t)(s * STAGE_ELEMS * 2);
#pragma unroll
        for (int it = 0; it < 2; it++) {
            uint32_t doff = (uint32_t)((ar[it] * LDA + akv[it]) * 2);
            cp16(sa + doff,               g_ahi + agi[it] + k0, asz[it]);
            cp16(sa + OFF_ALO * 2 + doff, g_alo + agi[it] + k0, asz[it]);
        }
#pragma unroll
        for (int it = 0; it < 2; it++) {
            uint32_t doff = (uint32_t)((br[it] * LDB + bnv[it]) * 2);
            size_t gi = bgi_rel[it] + (size_t)k0 * HHH;
            cp16(sa + OFF_BHI * 2 + doff, Bhi + gi, 16);
            cp16(sa + OFF_BLO * 2 + doff, Blo + gi, 16);
        }
        asm volatile("cp.async.commit_group;" ::: "memory");
    };

    wmma::fragment<wmma::accumulator, 16, 16, 16, float> acc[2][4];
#pragma unroll
    for (int i = 0; i < 2; i++)
#pragma unroll
        for (int j = 0; j < 4; j++) wmma::fill_fragment(acc[i][j], 0.f);

    load_stage(0, 0);

#pragma unroll 1
    for (int it = 0; it < 8; it++) {
        if (it < 7) {
            load_stage((it + 1) & 1, (it + 1) * BK);
            asm volatile("cp.async.wait_group 1;" ::: "memory");
        } else {
            asm volatile("cp.async.wait_group 0;" ::: "memory");
        }
        __syncthreads();

        const __nv_bfloat16* st = sm + (it & 1) * STAGE_ELEMS;
        const __nv_bfloat16* As_hi = st;
        const __nv_bfloat16* As_lo = st + OFF_ALO;
        const __nv_bfloat16* Bs_hi = st + OFF_BHI;
        const __nv_bfloat16* Bs_lo = st + OFF_BLO;

#pragma unroll
        for (int kk = 0; kk < BK; kk += 16) {
            wmma::fragment<wmma::matrix_a, 16, 16, 16, __nv_bfloat16, wmma::row_major> a_hi[2], a_lo[2];
#pragma unroll
            for (int i = 0; i < 2; i++) {
                wmma::load_matrix_sync(a_hi[i], As_hi + (wm * 32 + i * 16) * LDA + kk, LDA);
                wmma::load_matrix_sync(a_lo[i], As_lo + (wm * 32 + i * 16) * LDA + kk, LDA);
            }
#pragma unroll
            for (int j = 0; j < 4; j++) {
                wmma::fragment<wmma::matrix_b, 16, 16, 16, __nv_bfloat16, wmma::row_major> b_hi, b_lo;
                wmma::load_matrix_sync(b_hi, Bs_hi + kk * LDB + wn * 64 + j * 16, LDB);
                wmma::load_matrix_sync(b_lo, Bs_lo + kk * LDB + wn * 64 + j * 16, LDB);
#pragma unroll
                for (int i = 0; i < 2; i++) {
                    wmma::mma_sync(acc[i][j], a_hi[i], b_hi, acc[i][j]);
                    wmma::mma_sync(acc[i][j], a_hi[i], b_lo, acc[i][j]);
                    wmma::mma_sync(acc[i][j], a_lo[i], b_hi, acc[i][j]);
                }
            }
        }
        __syncthreads();
    }

    // epilogue: NN % 32 == 0, each 16-row tile fully in or out
#pragma unroll
    for (int i = 0; i < 2; i++) {
        int mrow = m0 + wm * 32 + i * 16;
        if (mrow + 16 <= NN) {
#pragma unroll
            for (int j = 0; j < 4; j++) {
                float* cp = C + (size_t)mrow * HHH + n0 + wn * 64 + j * 16;
                wmma::store_matrix_sync(cp, acc[i][j], HHH, wmma::mem_row_major);
            }
        }
    }
}

// ---------------- fused attention scores over CSR positions ----------------
// grid: (EA/64, HEADS); consecutive positions share dst -> xr row hits L1.
__global__ __launch_bounds__(256) void k_score_f(
    const float* __restrict__ edge_attr,
    const float* __restrict__ att, const float* __restrict__ We)
{
    int h = blockIdx.y;
    __shared__ float sW[BOND][HH];
    __shared__ float sAtt[HH];
    int tid = threadIdx.x, lane = tid & 31, w = tid >> 5;
    for (int idx = tid; idx < BOND * HH; idx += 256) {
        int k = idx >> 8, c = idx & 255;
        sW[k][c] = We[k * HHH + h * HH + c];
    }
    sAtt[tid] = att[h * HH + tid];
    __syncthreads();

    int p0 = blockIdx.x * 64;
#pragma unroll 1
    for (int q = w; q < 64; q += 8) {
        int pos = p0 + q;
        int e = g_elist[pos];
        int s = g_esrc[pos];
        int d = g_edst[pos];
        const float* eap = (e < EE) ? &edge_attr[(size_t)e * BOND] : &g_loop[(size_t)(e - EE) * BOND];
        float ea[BOND];
#pragma unroll
        for (int k = 0; k < BOND; k++) ea[k] = eap[k];
        const float* xl = &g_xl[(size_t)s * HHH + h * HH];
        const float* xr = &g_xr[(size_t)d * HHH + h * HH];
        float acc = 0.f;
#pragma unroll
        for (int i = 0; i < 8; i++) {
            int j = lane + 32 * i;
            float eev = 0.f;
#pragma unroll
            for (int k = 0; k < BOND; k++) eev += ea[k] * sW[k][j];
            float v = xl[j] + xr[j] + eev;
            v = (v > 0.f) ? v : NEG * v;
            acc += v * sAtt[j];
        }
        acc = warpRedSum(acc);
        if (lane == 0) g_score[pos * HEADS + h] = acc;
    }
}

// ---------------- fused per-node softmax/aggregate/LN ----------------
#define CHUNK 128
__global__ __launch_bounds__(256) void k_node(
    const float* __restrict__ bias,
    const float* __restrict__ lng, const float* __restrict__ lnb)
{
    int i = blockIdx.x, t = threadIdx.x, lane = t & 31, w = t >> 5;
    __shared__ float s_max[8], s_rcp[8];
    __shared__ float s_alpha[CHUNK * 8];
    __shared__ int   s_src[CHUNK];
    int beg = g_off[i], end = g_off[i + 1], m = end - beg;

    float mv = -3.4e38f;
    for (int p = lane; p < m; p += 32)
        mv = fmaxf(mv, g_score[(beg + p) * HEADS + w]);
    mv = warpRedMax(mv);
    if (lane == 0) s_max[w] = mv;
    __syncthreads();

    float mh = s_max[w];
    float sum = 0.f;
    for (int p = lane; p < m; p += 32)
        sum += expf(g_score[(beg + p) * HEADS + w] - mh);
    sum = warpRedSum(sum);
    if (lane == 0) s_rcp[w] = 1.0f / sum;
    __syncthreads();

    float acc[8];
#pragma unroll
    for (int h = 0; h < 8; h++) acc[h] = 0.f;
    for (int c0 = 0; c0 < m; c0 += CHUNK) {
        int cm = min(CHUNK, m - c0);
        for (int p = t; p < cm * 8; p += 256) {
            int idx = p >> 3, h = p & 7;
            s_alpha[p] = expf(g_score[(beg + c0 + idx) * HEADS + h] - s_max[h]) * s_rcp[h];
            if (h == 0) s_src[idx] = g_esrc[beg + c0 + idx];
        }
        __syncthreads();
        for (int idx = 0; idx < cm; idx++) {
            const float* xp = &g_xl[(size_t)s_src[idx] * HHH + t];
            const float* ap = &s_alpha[idx * 8];
#pragma unroll
            for (int h = 0; h < 8; h++) acc[h] += ap[h] * xp[h * HH];
        }
        __syncthreads();
    }

    float o = (acc[0] + acc[1] + acc[2] + acc[3] + acc[4] + acc[5] + acc[6] + acc[7]) * 0.125f
              + bias[t] + g_h[i * HH + t];
    float2 ss = blockReduce2_256(o, o * o);
    float mean = ss.x * (1.0f / HH);
    float var  = ss.y * (1.0f / HH) - mean * mean;
    store_h_split(i * HH + t, (o - mean) * rsqrtf(var + EPS) * lng[t] + lnb[t]);
}

// ---------------- readout ----------------
__global__ __launch_bounds__(128) void k_gate(
    const float* __restrict__ g1W, const float* __restrict__ g1b,
    const float* __restrict__ g2W, const float* __restrict__ g2b)
{
    int i = blockIdx.x, t = threadIdx.x;
    __shared__ float hs[HH];
    __shared__ float red[4];
    hs[t] = g_h[i * HH + t];
    hs[t + 128] = g_h[i * HH + t + 128];
    __syncthreads();
    float acc = g1b[t];
#pragma unroll 8
    for (int k = 0; k < HH; k++) acc += hs[k] * g1W[k * 128 + t];
    float v = fmaxf(acc, 0.f) * g2W[t];
    v = warpRedSum(v);
    if ((t & 31) == 0) red[t >> 5] = v;
    __syncthreads();
    if (t == 0) g_gate[i] = red[0] + red[1] + red[2] + red[3] + g2b[0];
}
__global__ void k_gmax(const int* __restrict__ batch) {
    int i = blockIdx.x * blockDim.x + threadIdx.x;
    if (i >= NN) return;
    atomicMaxF(&g_gmax[batch[i]], g_gate[i]);
}
__global__ void k_gsum(const int* __restrict__ batch) {
    int i = blockIdx.x * blockDim.x + threadIdx.x;
    if (i >= NN) return;
    float ge = expf(g_gate[i] - g_gmax[batch[i]]);
    g_ge[i] = ge;
    atomicAdd(&g_gsum[batch[i]], ge);
}
__global__ __launch_bounds__(256) void k_out(const int* __restrict__ batch, float* __restrict__ out) {
    int i = blockIdx.x, t = threadIdx.x;
    int b = batch[i];
    float w = g_ge[i] / fmaxf(g_gsum[b], 1e-16f);
    atomicAdd(&out[b * HH + t], w * g_h[i * HH + t]);
}

// ---------------- launch ----------------
extern "C" void kernel_launch(void* const* d_in, const int* in_sizes, int n_in,
                              void* d_out, int out_size)
{
    const float* x        = (const float*)d_in[0];
    const float* edge_attr= (const float*)d_in[1];
    const float* emb_W    = (const float*)d_in[2];
    const float* emb_b    = (const float*)d_in[3];
    const float* emb_g    = (const float*)d_in[4];
    const float* emb_beta = (const float*)d_in[5];
    const float* Wl       = (const float*)d_in[6];
    const float* Wr       = (const float*)d_in[7];
    const float* We       = (const float*)d_in[8];
    const float* att      = (const float*)d_in[9];
    const float* bias     = (const float*)d_in[10];
    const float* ln_g     = (const float*)d_in[11];
    const float* ln_b     = (const float*)d_in[12];
    const float* g1W      = (const float*)d_in[13];
    const float* g1b      = (const float*)d_in[14];
    const float* g2W      = (const float*)d_in[15];
    const float* g2b      = (const float*)d_in[16];
    const int*   ei       = (const int*)d_in[17];
    const int*   batch    = (const int*)d_in[18];
    float* out = (float*)d_out;

    cudaFuncSetAttribute(wgemm, cudaFuncAttributeMaxDynamicSharedMemorySize, WG_SMEM);

    // order chosen so launch #4 is wgemm (ncu -s 5 -c 1 window)
    k_init<<<(NN * BOND + 255) / 256, 256>>>(out);
    k_embed<<<NN, 256>>>(x, emb_W, emb_b, emb_g, emb_beta);
    k_cvtW<<<dim3((HH * HHH + 255) / 256, 2), 256>>>(Wl, Wr);
    wgemm<<<dim3(HHH / 128, (NN + 127) / 128, 2), 256, WG_SMEM>>>();

    k_count<<<(EE + 255) / 256, 256>>>(ei, edge_attr);
    k_loopfin<<<(NN * BOND + 255) / 256, 256>>>();
    k_scan<<<1, 1024>>>();
    k_fill<<<(EA + 255) / 256, 256>>>(ei);

    k_score_f<<<dim3(EA / 64, HEADS), 256>>>(edge_attr, att, We);
    k_node<<<NN, 256>>>(bias, ln_g, ln_b);

    for (int l = 1; l < LL; l++) {
        k_cvtW<<<dim3((HH * HHH + 255) / 256, 2), 256>>>(
            Wl + (size_t)l * HH * HHH, Wr + (size_t)l * HH * HHH);
        wgemm<<<dim3(HHH / 128, (NN + 127) / 128, 2), 256, WG_SMEM>>>();
        k_score_f<<<dim3(EA / 64, HEADS), 256>>>(
            edge_attr, att + (size_t)l * HEADS * HH, We + (size_t)l * BOND * HHH);
        k_node<<<NN, 256>>>(bias + l * HH, ln_g + l * HH, ln_b + l * HH);
    }

    k_gate<<<NN, 128>>>(g1W, g1b, g2W, g2b);
    k_gmax<<<(NN + 255) / 256, 256>>>(batch);
    k_gsum<<<(NN + 255) / 256, 256>>>(batch);
    k_out<<<NN, 256>>>(batch, out);
}